// round 9
// baseline (speedup 1.0000x reference)
#include <cuda_runtime.h>
#include <cstdint>

#define M_SZ    100
#define H_SZ    256
#define W_SZ    512
#define N_INST  64
#define C_THING 80
#define C_STUFF 53
#define C_OUT   (C_STUFF + N_INST)      // 117
#define ROW_B   (W_SZ * 4)              // 2048 bytes/row
#define CHUNK_ROWS 4
#define CHUNK_B (CHUNK_ROWS * ROW_B)    // 8192
#define QROWS   64                      // rows per CTA (quarter channel)
#define NCHUNK  (QROWS / CHUNK_ROWS)    // 16
#define NBUF    4

__device__ __forceinline__ uint32_t smem_u32(const void* p) {
    uint32_t a;
    asm("{ .reg .u64 t; cvta.to.shared.u64 t, %1; cvt.u32.u64 %0, t; }"
        : "=r"(a) : "l"(p));
    return a;
}
__device__ __forceinline__ void mbar_init(uint32_t mbar, uint32_t cnt) {
    asm volatile("mbarrier.init.shared.b64 [%0], %1;" :: "r"(mbar), "r"(cnt) : "memory");
}
__device__ __forceinline__ void mbar_expect_tx(uint32_t mbar, uint32_t bytes) {
    asm volatile("mbarrier.arrive.expect_tx.shared.b64 _, [%0], %1;"
                 :: "r"(mbar), "r"(bytes) : "memory");
}
__device__ __forceinline__ void mbar_wait(uint32_t mbar, int parity) {
    asm volatile(
        "{\n\t.reg .pred P;\n"
        "W%=:\n\t"
        "mbarrier.try_wait.parity.shared::cta.b64 P, [%0], %1;\n\t"
        "@P bra D%=;\n\t"
        "bra W%=;\n"
        "D%=:\n\t}"
        :: "r"(mbar), "r"(parity) : "memory");
}
__device__ __forceinline__ void bulk_load(uint32_t smem, const void* gmem,
                                          uint32_t bytes, uint32_t mbar) {
    asm volatile(
        "cp.async.bulk.shared::cta.global.mbarrier::complete_tx::bytes [%0], [%1], %2, [%3];"
        :: "r"(smem), "l"(gmem), "r"(bytes), "r"(mbar) : "memory");
}
__device__ __forceinline__ void bulk_store(void* gmem, uint32_t smem, uint32_t bytes) {
    asm volatile(
        "cp.async.bulk.global.shared::cta.bulk_group [%0], [%1], %2;"
        :: "l"(gmem), "r"(smem), "r"(bytes) : "memory");
}
__device__ __forceinline__ void bulk_commit() {
    asm volatile("cp.async.bulk.commit_group;" ::: "memory");
}
__device__ __forceinline__ void bulk_wait_read1() {
    asm volatile("cp.async.bulk.wait_group.read 1;" ::: "memory");
}
__device__ __forceinline__ void bulk_wait_all() {
    asm volatile("cp.async.bulk.wait_group 0;" ::: "memory");
}
__device__ __forceinline__ void fence_async() {
    asm volatile("fence.proxy.async;" ::: "memory");
}

// 468 CTAs: blockIdx.x -> (channel = b>>2, quarter = b&3) = 64 rows.
// Stuff channel quarters: pipelined bulk copy (4x8KB ring, 3-deep lookahead).
// Thing channel quarters: bulk-store zeros from a zeroed SMEM buffer for
// 4-row chunks outside the box-row union; SM compute for chunks inside.
__global__ __launch_bounds__(128)
void panoptic_tma_kernel(const float* __restrict__ mask_logits,   // [N, C_THING, M, M]
                         const float* __restrict__ sem_seg,       // [1, C_STUFF+C_THING, H, W]
                         const float* __restrict__ bbox,          // [N, 4]
                         const int*   __restrict__ cls_idx,       // [N]
                         float* __restrict__ out)                 // [1, C_OUT, H, W]
{
    __shared__ __align__(128) char sbuf[NBUF * CHUNK_B];          // 32 KB
    __shared__ __align__(8)  unsigned long long mbar_s[NBUF];

    const int tid  = threadIdx.x;
    const int wid  = tid >> 5;
    const int lane = tid & 31;
    const int c    = blockIdx.x >> 2;
    const int q    = blockIdx.x & 3;
    const int y0   = q * QROWS;
    const size_t rowbase = (size_t)c * H_SZ + y0;                 // first row

    if (c < C_STUFF) {
        // ---------------- stuff: pipelined bulk copy ----------------
        if (tid != 0) return;
        const uint32_t sb = smem_u32(sbuf);
        const uint32_t mb = smem_u32(mbar_s);
        #pragma unroll
        for (int j = 0; j < NBUF; ++j) mbar_init(mb + 8 * j, 1);
        fence_async();

        const char* src = (const char*)sem_seg + rowbase * ROW_B;
        char*       dst = (char*)out          + rowbase * ROW_B;

        int ph[NBUF] = {0, 0, 0, 0};
        #pragma unroll
        for (int j = 0; j < 3; ++j) {                 // lookahead 3
            mbar_expect_tx(mb + 8 * j, CHUNK_B);
            bulk_load(sb + j * CHUNK_B, src + (size_t)j * CHUNK_B, CHUNK_B, mb + 8 * j);
        }
        for (int i = 0; i < NCHUNK; ++i) {
            const int b = i & (NBUF - 1);
            mbar_wait(mb + 8 * b, ph[b]); ph[b] ^= 1;
            bulk_store(dst + (size_t)i * CHUNK_B, sb + b * CHUNK_B, CHUNK_B);
            bulk_commit();
            const int j = i + 3;
            if (j < NCHUNK) {
                bulk_wait_read1();                    // buffer (j&3)'s prior store read-done
                const int b2 = j & (NBUF - 1);
                mbar_expect_tx(mb + 8 * b2, CHUNK_B);
                bulk_load(sb + b2 * CHUNK_B, src + (size_t)j * CHUNK_B, CHUNK_B, mb + 8 * b2);
            }
        }
        bulk_wait_all();
        return;
    }

    // ---------------- thing channel quarter ----------------
    const int n = c - C_STUFF;

    // zero the first 8KB of sbuf for bulk zero-stores
    {
        float4* zb = (float4*)sbuf;
        #pragma unroll
        for (int k = 0; k < 4; ++k) zb[tid + 128 * k] = make_float4(0.f, 0.f, 0.f, 0.f);
        fence_async();
        __syncthreads();
    }

    const float bx1 = __ldg(&bbox[n * 4 + 0]);
    const float by1 = __ldg(&bbox[n * 4 + 1]);
    const float bx2 = __ldg(&bbox[n * 4 + 2]);
    const float by2 = __ldg(&bbox[n * 4 + 3]);
    const int   cls = __ldg(&cls_idx[n]);

    const int x1b = (int)floorf(bx1);
    const int y1b = (int)floorf(by1);
    const int x2b = (int)floorf(bx2);
    const int y2b = (int)floorf(by2);
    const int cy2 = (int)rintf(by2) + 1;        // crop row end (>= y2b+1)
    const int cx2 = (int)rintf(bx2) + 1;

    const int by_lo = y1b;                      // nonzero-row union start (cy1 == y1b)
    const int by_hi = min(cy2, H_SZ);           // nonzero-row union end

    const int  pyhi  = min(y2b + 1, H_SZ);
    const int  xhi   = min(x2b + 1, W_SZ);
    const float invbw = (float)M_SZ / (float)(x2b - x1b + 1);
    const float invbh = (float)M_SZ / (float)(y2b - y1b + 1);
    const float* __restrict__ mtile =
        mask_logits + ((size_t)n * C_THING + (size_t)cls) * (M_SZ * M_SZ);
    const float* __restrict__ schan =
        sem_seg + (size_t)(C_STUFF + cls) * H_SZ * W_SZ;

    const uint32_t zb = smem_u32(sbuf);
    char* dstq = (char*)out + rowbase * ROW_B;

    for (int k = 0; k < NCHUNK; ++k) {
        const int cy = y0 + k * CHUNK_ROWS;                    // global row of chunk
        const bool overlap = !(cy + CHUNK_ROWS <= by_lo || cy >= by_hi);
        if (!overlap) {
            if (tid == 0)
                bulk_store(dstq + (size_t)k * CHUNK_B, zb, CHUNK_B);
            continue;
        }
        // compute all 4 rows: warp wid handles row cy+wid
        const int y = cy + wid;
        float4* __restrict__ orow =
            (float4*)(out + ((size_t)(C_STUFF + n) * H_SZ + (size_t)y) * W_SZ);

        const bool in_paste = (y >= y1b) && (y < pyhi);
        const bool in_crop  = (y >= y1b) && (y < cy2);

        float4 vals[4];
        #pragma unroll
        for (int j = 0; j < 4; ++j) vals[j] = make_float4(0.f, 0.f, 0.f, 0.f);

        if (in_paste) {
            float my = ((float)y - (float)y1b + 0.5f) * invbh - 0.5f;
            my = fmaxf(my, 0.f);
            const float myf = floorf(my);
            const float fy  = my - myf;
            const int iy0 = min((int)myf,     M_SZ - 1);
            const int iy1 = min((int)myf + 1, M_SZ - 1);
            const float* __restrict__ mrow0 = mtile + iy0 * M_SZ;
            const float* __restrict__ mrow1 = mtile + iy1 * M_SZ;
            #pragma unroll
            for (int j = 0; j < 4; ++j) {
                const int xbase = (lane + 32 * j) * 4;
                if (xbase + 3 < x1b || xbase >= xhi) continue;
                float* v = &vals[j].x;
                #pragma unroll
                for (int e = 0; e < 4; ++e) {
                    const int x = xbase + e;
                    if (x >= x1b && x < xhi) {
                        float mx = ((float)x - (float)x1b + 0.5f) * invbw - 0.5f;
                        mx = fmaxf(mx, 0.f);
                        const float mxf = floorf(mx);
                        const float fx  = mx - mxf;
                        const int ix0 = min((int)mxf,     M_SZ - 1);
                        const int ix1 = min((int)mxf + 1, M_SZ - 1);
                        const float top = mrow0[ix0] * (1.f - fx) + mrow0[ix1] * fx;
                        const float bot = mrow1[ix0] * (1.f - fx) + mrow1[ix1] * fx;
                        v[e] = (1.f - fy) * top + fy * bot;
                    }
                }
            }
        }
        if (in_crop) {
            const float* __restrict__ srow = schan + (size_t)y * W_SZ;
            #pragma unroll
            for (int j = 0; j < 4; ++j) {
                const int xbase = (lane + 32 * j) * 4;
                if (xbase + 3 < x1b || xbase >= cx2) continue;
                float* v = &vals[j].x;
                if (xbase >= x1b && xbase + 3 < cx2) {
                    const float4 s = *(const float4*)(srow + xbase);
                    v[0] += s.x; v[1] += s.y; v[2] += s.z; v[3] += s.w;
                } else {
                    #pragma unroll
                    for (int e = 0; e < 4; ++e) {
                        const int x = xbase + e;
                        if (x >= x1b && x < cx2) v[e] += __ldg(&srow[x]);
                    }
                }
            }
        }
        orow[lane]      = vals[0];
        orow[lane + 32] = vals[1];
        orow[lane + 64] = vals[2];
        orow[lane + 96] = vals[3];
    }

    if (tid == 0) { bulk_commit(); bulk_wait_all(); }
}

extern "C" void kernel_launch(void* const* d_in, const int* in_sizes, int n_in,
                              void* d_out, int out_size)
{
    const float* mask_logits = (const float*)d_in[0];
    const float* sem_seg     = (const float*)d_in[1];
    const float* bbox        = (const float*)d_in[2];
    const int*   cls_idx     = (const int*)d_in[3];
    float*       out         = (float*)d_out;

    panoptic_tma_kernel<<<C_OUT * 4, 128>>>(mask_logits, sem_seg, bbox, cls_idx, out);
}

// round 10
// speedup vs baseline: 2.1600x; 2.1600x over previous
#include <cuda_runtime.h>

#define M_SZ    100
#define H_SZ    256
#define W_SZ    512
#define N_INST  64
#define C_THING 80
#define C_STUFF 53
#define C_OUT   (C_STUFF + N_INST)   // 117
#define WARPS_PB 8

// ---------------- Kernel A: pure streaming (copy stuff / zero things) -------
// One warp per output row. No bbox logic, no divergence: c<53 -> copy, else 0.
__global__ __launch_bounds__(WARPS_PB * 32)
void panoptic_stream_kernel(const float* __restrict__ sem_seg,   // [1,133,H,W]
                            float* __restrict__ out)             // [1,117,H,W]
{
    const int warp = threadIdx.x >> 5;
    const int lane = threadIdx.x & 31;
    const int grow = blockIdx.x * WARPS_PB + warp;      // [0, C_OUT*H)

    float4* __restrict__ orow = (float4*)(out + (size_t)grow * W_SZ);

    if ((grow >> 8) < C_STUFF) {
        const float4* __restrict__ srow =
            (const float4*)(sem_seg + (size_t)grow * W_SZ);
        float4 v0 = srow[lane];
        float4 v1 = srow[lane + 32];
        float4 v2 = srow[lane + 64];
        float4 v3 = srow[lane + 96];
        orow[lane]      = v0;
        orow[lane + 32] = v1;
        orow[lane + 64] = v2;
        orow[lane + 96] = v3;
    } else {
        const float4 z = make_float4(0.f, 0.f, 0.f, 0.f);
        orow[lane]      = z;
        orow[lane + 32] = z;
        orow[lane + 64] = z;
        orow[lane + 96] = z;
    }
}

// ---------------- Kernel B: box rows only (overwrites A's zeros) ------------
// blockIdx.y = instance, blockIdx.x = row group (8 rows). Warp threadIdx.y
// handles row y1b + 8*bx + ty; lane covers x = x1b + lane + 32k, k<3.
__global__ __launch_bounds__(256)
void panoptic_box_kernel(const float* __restrict__ mask_logits,   // [N,80,M,M]
                         const float* __restrict__ sem_seg,       // [1,133,H,W]
                         const float* __restrict__ bbox,          // [N,4]
                         const int*   __restrict__ cls_idx,       // [N]
                         float* __restrict__ out)                 // [1,117,H,W]
{
    const int n    = blockIdx.y;
    const int lane = threadIdx.x;

    const float bx1 = __ldg(&bbox[n * 4 + 0]);
    const float by1 = __ldg(&bbox[n * 4 + 1]);
    const float bx2 = __ldg(&bbox[n * 4 + 2]);
    const float by2 = __ldg(&bbox[n * 4 + 3]);
    const int   cls = __ldg(&cls_idx[n]);

    // paste box (floor); crop box start == floor (coords>=0), end = round+1.
    const int x1b = (int)floorf(bx1);
    const int y1b = (int)floorf(by1);
    const int x2b = (int)floorf(bx2);
    const int y2b = (int)floorf(by2);
    const int cy2 = (int)rintf(by2) + 1;   // >= y2b+1
    const int cx2 = (int)rintf(bx2) + 1;   // >= x2b+1

    const int rend = min(cy2, H_SZ);       // row union end
    const int xend = min(cx2, W_SZ);       // col union end

    const int y = y1b + blockIdx.x * 8 + threadIdx.y;
    if (y >= rend) return;

    const int  pyhi     = min(y2b + 1, H_SZ);
    const bool in_paste = (y < pyhi);      // y >= y1b by construction
    const bool in_crop  = (y < cy2);

    const float* __restrict__ mrow0 = nullptr;
    const float* __restrict__ mrow1 = nullptr;
    float fy = 0.f;
    const int xhi = min(x2b + 1, W_SZ);
    const float invbw = (float)M_SZ / (float)(x2b - x1b + 1);

    if (in_paste) {
        const float* __restrict__ mtile =
            mask_logits + ((size_t)n * C_THING + (size_t)cls) * (M_SZ * M_SZ);
        float my = ((float)y - (float)y1b + 0.5f) *
                   ((float)M_SZ / (float)(y2b - y1b + 1)) - 0.5f;
        my = fmaxf(my, 0.f);
        const float myf = floorf(my);
        fy = my - myf;
        const int iy0 = min((int)myf,     M_SZ - 1);
        const int iy1 = min((int)myf + 1, M_SZ - 1);
        mrow0 = mtile + iy0 * M_SZ;
        mrow1 = mtile + iy1 * M_SZ;
    }

    const float* __restrict__ srow =
        sem_seg + ((size_t)(C_STUFF + cls) * H_SZ + (size_t)y) * W_SZ;
    float* __restrict__ orow =
        out + ((size_t)(C_STUFF + n) * H_SZ + (size_t)y) * W_SZ;

    #pragma unroll
    for (int k = 0; k < 3; ++k) {
        const int x = x1b + lane + 32 * k;
        if (x >= xend) break;
        float val = 0.f;
        if (in_paste && x < xhi) {
            float mx = ((float)x - (float)x1b + 0.5f) * invbw - 0.5f;
            mx = fmaxf(mx, 0.f);
            const float mxf = floorf(mx);
            const float fx  = mx - mxf;
            const int ix0 = min((int)mxf,     M_SZ - 1);
            const int ix1 = min((int)mxf + 1, M_SZ - 1);
            const float top = mrow0[ix0] * (1.f - fx) + mrow0[ix1] * fx;
            const float bot = mrow1[ix0] * (1.f - fx) + mrow1[ix1] * fx;
            val = (1.f - fy) * top + fy * bot;
        }
        if (in_crop && x < cx2) {
            val += __ldg(&srow[x]);
        }
        orow[x] = val;
    }
}

extern "C" void kernel_launch(void* const* d_in, const int* in_sizes, int n_in,
                              void* d_out, int out_size)
{
    const float* mask_logits = (const float*)d_in[0];
    const float* sem_seg     = (const float*)d_in[1];
    const float* bbox        = (const float*)d_in[2];
    const int*   cls_idx     = (const int*)d_in[3];
    float*       out         = (float*)d_out;

    // A: pure streaming over all rows
    const int total_rows = C_OUT * H_SZ;                 // 29952
    panoptic_stream_kernel<<<total_rows / WARPS_PB, WARPS_PB * 32>>>(sem_seg, out);

    // B: overwrite box-union rows (depends on A via stream order)
    dim3 gridB(10, N_INST);          // 10 row-groups x 64 instances (80 >= max span)
    dim3 blockB(32, 8);              // warp per row
    panoptic_box_kernel<<<gridB, blockB>>>(mask_logits, sem_seg, bbox, cls_idx, out);
}

// round 11
// speedup vs baseline: 2.8673x; 1.3274x over previous
#include <cuda_runtime.h>

#define M_SZ    100
#define H_SZ    256
#define W_SZ    512
#define N_INST  64
#define C_THING 80
#define C_STUFF 53
#define C_OUT   (C_STUFF + N_INST)   // 117
#define WARPS_PB 8
#define BOX_BLOCKS (N_INST * 10)     // 640: 10 row-groups x 64 instances
#define STREAM_BLOCKS (C_OUT * H_SZ / WARPS_PB)  // 3744

// Single launch. blockIdx.x < BOX_BLOCKS: box work (writes only columns inside
// [x1b, xend) of rows in the box row-union). Otherwise: streaming work (copies
// stuff rows; zeroes thing rows EXCEPT the in-box columns). Writes are
// element-disjoint across blocks -> no ordering required.
__global__ __launch_bounds__(256)
void panoptic_fused_kernel(const float* __restrict__ mask_logits,   // [N,80,M,M]
                           const float* __restrict__ sem_seg,       // [1,133,H,W]
                           const float* __restrict__ bbox,          // [N,4]
                           const int*   __restrict__ cls_idx,       // [N]
                           float* __restrict__ out)                 // [1,117,H,W]
{
    const int tid  = threadIdx.x;
    const int lane = tid & 31;

    if (blockIdx.x >= BOX_BLOCKS) {
        // ================= streaming part =================
        const int warp = tid >> 5;
        const int grow = (blockIdx.x - BOX_BLOCKS) * WARPS_PB + warp;
        const int c    = grow >> 8;                     // H == 256
        float4* __restrict__ orow = (float4*)(out + (size_t)grow * W_SZ);

        if (c < C_STUFF) {
            const float4* __restrict__ srow =
                (const float4*)(sem_seg + (size_t)grow * W_SZ);
            float4 v0 = srow[lane];
            float4 v1 = srow[lane + 32];
            float4 v2 = srow[lane + 64];
            float4 v3 = srow[lane + 96];
            orow[lane]      = v0;
            orow[lane + 32] = v1;
            orow[lane + 64] = v2;
            orow[lane + 96] = v3;
            return;
        }

        const int n = c - C_STUFF;
        const int y = grow & (H_SZ - 1);

        const float bx1 = __ldg(&bbox[n * 4 + 0]);
        const float by1 = __ldg(&bbox[n * 4 + 1]);
        const float bx2 = __ldg(&bbox[n * 4 + 2]);
        const float by2 = __ldg(&bbox[n * 4 + 3]);

        const int x1b  = (int)floorf(bx1);
        const int y1b  = (int)floorf(by1);
        const int cy2  = (int)rintf(by2) + 1;
        const int cx2  = (int)rintf(bx2) + 1;
        const int rend = min(cy2, H_SZ);     // row union end
        const int xend = min(cx2, W_SZ);     // col union end

        const float4 z = make_float4(0.f, 0.f, 0.f, 0.f);
        const bool row_in_union = (y >= y1b) && (y < rend);

        if (!row_in_union) {
            orow[lane]      = z;
            orow[lane + 32] = z;
            orow[lane + 64] = z;
            orow[lane + 96] = z;
            return;
        }

        // zero only columns outside [x1b, xend); box block owns the inside
        float* __restrict__ orowf = (float*)orow;
        #pragma unroll
        for (int j = 0; j < 4; ++j) {
            const int idx   = lane + 32 * j;
            const int xbase = idx * 4;
            if (xbase + 3 < x1b || xbase >= xend) {
                orow[idx] = z;                       // fully outside: vector zero
            } else if (xbase >= x1b && xbase + 3 < xend) {
                // fully inside: box block writes it
            } else {
                #pragma unroll
                for (int e = 0; e < 4; ++e) {
                    const int x = xbase + e;
                    if (x < x1b || x >= xend) orowf[x] = 0.f;
                }
            }
        }
        return;
    }

    // ================= box part =================
    const int bb = blockIdx.x;
    const int n  = bb & (N_INST - 1);               // 64 instances
    const int rg = bb >> 6;                          // 10 row groups

    const float bx1 = __ldg(&bbox[n * 4 + 0]);
    const float by1 = __ldg(&bbox[n * 4 + 1]);
    const float bx2 = __ldg(&bbox[n * 4 + 2]);
    const float by2 = __ldg(&bbox[n * 4 + 3]);
    const int   cls = __ldg(&cls_idx[n]);

    const int x1b = (int)floorf(bx1);
    const int y1b = (int)floorf(by1);
    const int x2b = (int)floorf(bx2);
    const int y2b = (int)floorf(by2);
    const int cy2 = (int)rintf(by2) + 1;
    const int cx2 = (int)rintf(bx2) + 1;

    const int rend = min(cy2, H_SZ);
    const int xend = min(cx2, W_SZ);

    const int y = y1b + rg * 8 + (tid >> 5);
    if (y >= rend) return;

    const int  pyhi     = min(y2b + 1, H_SZ);
    const bool in_paste = (y < pyhi);               // y >= y1b by construction
    const bool in_crop  = (y < cy2);

    const float* __restrict__ mrow0 = nullptr;
    const float* __restrict__ mrow1 = nullptr;
    float fy = 0.f;
    const int xhi = min(x2b + 1, W_SZ);
    const float invbw = (float)M_SZ / (float)(x2b - x1b + 1);

    if (in_paste) {
        const float* __restrict__ mtile =
            mask_logits + ((size_t)n * C_THING + (size_t)cls) * (M_SZ * M_SZ);
        float my = ((float)y - (float)y1b + 0.5f) *
                   ((float)M_SZ / (float)(y2b - y1b + 1)) - 0.5f;
        my = fmaxf(my, 0.f);
        const float myf = floorf(my);
        fy = my - myf;
        const int iy0 = min((int)myf,     M_SZ - 1);
        const int iy1 = min((int)myf + 1, M_SZ - 1);
        mrow0 = mtile + iy0 * M_SZ;
        mrow1 = mtile + iy1 * M_SZ;
    }

    const float* __restrict__ srow =
        sem_seg + ((size_t)(C_STUFF + cls) * H_SZ + (size_t)y) * W_SZ;
    float* __restrict__ orow =
        out + ((size_t)(C_STUFF + n) * H_SZ + (size_t)y) * W_SZ;

    #pragma unroll
    for (int k = 0; k < 3; ++k) {
        const int x = x1b + lane + 32 * k;
        if (x >= xend) break;
        float val = 0.f;
        if (in_paste && x < xhi) {
            float mx = ((float)x - (float)x1b + 0.5f) * invbw - 0.5f;
            mx = fmaxf(mx, 0.f);
            const float mxf = floorf(mx);
            const float fx  = mx - mxf;
            const int ix0 = min((int)mxf,     M_SZ - 1);
            const int ix1 = min((int)mxf + 1, M_SZ - 1);
            const float top = mrow0[ix0] * (1.f - fx) + mrow0[ix1] * fx;
            const float bot = mrow1[ix0] * (1.f - fx) + mrow1[ix1] * fx;
            val = (1.f - fy) * top + fy * bot;
        }
        if (in_crop && x < cx2) {
            val += __ldg(&srow[x]);
        }
        orow[x] = val;
    }
}

extern "C" void kernel_launch(void* const* d_in, const int* in_sizes, int n_in,
                              void* d_out, int out_size)
{
    const float* mask_logits = (const float*)d_in[0];
    const float* sem_seg     = (const float*)d_in[1];
    const float* bbox        = (const float*)d_in[2];
    const int*   cls_idx     = (const int*)d_in[3];
    float*       out         = (float*)d_out;

    panoptic_fused_kernel<<<BOX_BLOCKS + STREAM_BLOCKS, 256>>>(
        mask_logits, sem_seg, bbox, cls_idx, out);
}